// round 4
// baseline (speedup 1.0000x reference)
#include <cuda_runtime.h>
#include <math.h>

#define N_ROWS 8192
#define N_COLS 512
#define GRID_A 512
#define THREADS_A 256
#define WARPS_A 8              /* 512 blocks * 8 warps * 2 rows = 8192 rows */

#define SCALE_D   4294967296.0          /* 2^32 */
#define INV_SCALE (1.0 / 4294967296.0)

// Order-invariant integer accumulators (zero-init; last block resets).
__device__ unsigned long long g_col_ll[N_COLS];
__device__ unsigned long long g_S_ll;
__device__ int g_max_int;               // bit-cast float, values >= 0
__device__ unsigned int g_counter;

__global__ void __launch_bounds__(THREADS_A, 4)
fused_loss_kernel(const float* __restrict__ x, float* __restrict__ out) {
    __shared__ float s_colw[WARPS_A][N_COLS];   // 16 KB
    __shared__ float s_S[WARPS_A];
    __shared__ float s_M[WARPS_A];
    __shared__ double s_red[THREADS_A];
    __shared__ unsigned int s_last;

    const int tid = threadIdx.x;
    const int wid = tid >> 5;
    const int lid = tid & 31;

    // ---- streaming: warp owns 2 rows; ALL 8 float4 loads issued up front ----
    const int row0 = (blockIdx.x * WARPS_A + wid) * 2;
    const float4* p0 = reinterpret_cast<const float4*>(x + (size_t)row0 * N_COLS);
    const float4* p1 = reinterpret_cast<const float4*>(x + (size_t)(row0 + 1) * N_COLS);

    float4 v[8];
    #pragma unroll
    for (int p = 0; p < 4; ++p) v[p] = p0[p * 32 + lid];
    #pragma unroll
    for (int p = 0; p < 4; ++p) v[4 + p] = p1[p * 32 + lid];

    float sq0 = 0.f, sq1 = 0.f;
    #pragma unroll
    for (int p = 0; p < 4; ++p) {
        const float4 a = v[p];
        const float4 b = v[4 + p];
        float4 cs;
        cs.x = a.x + b.x; cs.y = a.y + b.y; cs.z = a.z + b.z; cs.w = a.w + b.w;
        *reinterpret_cast<float4*>(&s_colw[wid][p * 128 + lid * 4]) = cs;
        sq0 += a.x * a.x + a.y * a.y + a.z * a.z + a.w * a.w;
        sq1 += b.x * b.x + b.y * b.y + b.z * b.z + b.w * b.w;
    }

    // warp-reduce both row norms
    #pragma unroll
    for (int off = 16; off > 0; off >>= 1) {
        sq0 += __shfl_xor_sync(0xffffffffu, sq0, off);
        sq1 += __shfl_xor_sync(0xffffffffu, sq1, off);
    }
    if (lid == 0) {
        s_S[wid] = sq0 + sq1;
        s_M[wid] = fmaxf(sq0, sq1);
    }
    __syncthreads();

    // ---- block epilogue: combine 8 warps (vectorized), push int64 atomics ----
    {
        // thread t handles float4 chunk t (cols 4t..4t+3); 128 chunks, 256 thr:
        // threads 0..127 chunk tid, threads 128..255 idle for the vector part?
        // Instead: each thread handles one float4 chunk of 2 (512 cols = 128 chunks).
        // Use threads 0..127 for chunks, each sums 8 warps (8 LDS.128).
        if (tid < 128) {
            float4 acc = make_float4(0.f, 0.f, 0.f, 0.f);
            #pragma unroll
            for (int w = 0; w < WARPS_A; ++w) {
                const float4 t = *reinterpret_cast<const float4*>(&s_colw[w][tid * 4]);
                acc.x += t.x; acc.y += t.y; acc.z += t.z; acc.w += t.w;
            }
            const int c = tid * 4;
            atomicAdd(&g_col_ll[c + 0], (unsigned long long)__double2ll_rn((double)acc.x * SCALE_D));
            atomicAdd(&g_col_ll[c + 1], (unsigned long long)__double2ll_rn((double)acc.y * SCALE_D));
            atomicAdd(&g_col_ll[c + 2], (unsigned long long)__double2ll_rn((double)acc.z * SCALE_D));
            atomicAdd(&g_col_ll[c + 3], (unsigned long long)__double2ll_rn((double)acc.w * SCALE_D));
        }
    }
    if (tid == 0) {
        float Sp = 0.f, Mp = 0.f;
        #pragma unroll
        for (int w = 0; w < WARPS_A; ++w) {
            Sp += s_S[w];
            Mp = fmaxf(Mp, s_M[w]);
        }
        atomicAdd(&g_S_ll, (unsigned long long)__double2ll_rn((double)Sp * SCALE_D));
        atomicMax(&g_max_int, __float_as_int(Mp));
        __threadfence();
        const unsigned int prev = atomicAdd(&g_counter, 1u);
        s_last = (prev == (unsigned int)(GRID_A - 1)) ? 1u : 0u;
    }
    __syncthreads();
    if (s_last == 0u) return;

    // ---- finalize: last block; accumulators are tiny ----
    __threadfence();

    const unsigned long long c0 = g_col_ll[tid];
    const unsigned long long c1 = g_col_ll[tid + THREADS_A];
    const double d0 = (double)(long long)c0 * INV_SCALE;
    const double d1 = (double)(long long)c1 * INV_SCALE;

    s_red[tid] = d0 * d0 + d1 * d1;
    __syncthreads();
    #pragma unroll
    for (int s = THREADS_A / 2; s > 0; s >>= 1) {
        if (tid < s) s_red[tid] += s_red[tid + s];
        __syncthreads();
    }

    if (tid == 0) {
        const double ssq_total = s_red[0];
        const double S_total = (double)(long long)g_S_ll * INV_SCALE;
        const double maxsq = (double)__int_as_float(g_max_int);
        const double numer = (double)N_ROWS * S_total - ssq_total;
        const double norm = sqrt(maxsq);
        const double count = (double)N_ROWS * (double)(N_ROWS - 1) * 0.5;
        out[0] = (float)(numer / (norm * count));
        // reset scalars for next graph replay
        g_S_ll = 0ull;
        g_max_int = 0;
        g_counter = 0u;
    }
    // reset column accumulators
    g_col_ll[tid] = 0ull;
    g_col_ll[tid + THREADS_A] = 0ull;
}

extern "C" void kernel_launch(void* const* d_in, const int* in_sizes, int n_in,
                              void* d_out, int out_size) {
    (void)in_sizes; (void)n_in; (void)out_size;
    const float* x = (const float*)d_in[0];
    float* out = (float*)d_out;
    fused_loss_kernel<<<GRID_A, THREADS_A>>>(x, out);
}

// round 5
// speedup vs baseline: 2.2800x; 2.2800x over previous
#include <cuda_runtime.h>
#include <math.h>

#define N_ROWS 8192
#define N_COLS 512
#define GRID_A 512
#define THREADS_A 256
#define WARPS_A 8              /* 512 blocks * 8 warps * 2 rows = 8192 rows */
#define NREP 8                 /* column-accumulator replicas */

#define SCALE_D   4294967296.0          /* 2^32 */
#define INV_SCALE (1.0 / 4294967296.0)

// Order-invariant integer accumulators (zero-init; last block resets).
__device__ unsigned long long g_col_ll[NREP][N_COLS];
__device__ unsigned long long g_S_ll;
__device__ int g_max_int;               // bit-cast float, values >= 0
__device__ unsigned int g_counter;

__global__ void __launch_bounds__(THREADS_A, 3)
fused_loss_kernel(const float* __restrict__ x, float* __restrict__ out) {
    __shared__ float s_colw[WARPS_A][N_COLS];   // 16 KB
    __shared__ float s_S[WARPS_A];
    __shared__ float s_M[WARPS_A];
    __shared__ double s_red[THREADS_A];
    __shared__ unsigned int s_last;

    const int tid = threadIdx.x;
    const int wid = tid >> 5;
    const int lid = tid & 31;

    // ---- streaming: warp owns 2 rows; 8 named float4 loads, all up front ----
    const int row0 = (blockIdx.x * WARPS_A + wid) * 2;
    const float4* p0 = reinterpret_cast<const float4*>(x + (size_t)row0 * N_COLS);
    const float4* p1 = reinterpret_cast<const float4*>(x + (size_t)(row0 + 1) * N_COLS);

    const float4 a0 = p0[lid];
    const float4 a1 = p0[32 + lid];
    const float4 a2 = p0[64 + lid];
    const float4 a3 = p0[96 + lid];
    const float4 b0 = p1[lid];
    const float4 b1 = p1[32 + lid];
    const float4 b2 = p1[64 + lid];
    const float4 b3 = p1[96 + lid];

    // column partials into smem (vectorized)
    float4 c0, c1, c2, c3;
    c0.x = a0.x + b0.x; c0.y = a0.y + b0.y; c0.z = a0.z + b0.z; c0.w = a0.w + b0.w;
    c1.x = a1.x + b1.x; c1.y = a1.y + b1.y; c1.z = a1.z + b1.z; c1.w = a1.w + b1.w;
    c2.x = a2.x + b2.x; c2.y = a2.y + b2.y; c2.z = a2.z + b2.z; c2.w = a2.w + b2.w;
    c3.x = a3.x + b3.x; c3.y = a3.y + b3.y; c3.z = a3.z + b3.z; c3.w = a3.w + b3.w;
    *reinterpret_cast<float4*>(&s_colw[wid][0   + lid * 4]) = c0;
    *reinterpret_cast<float4*>(&s_colw[wid][128 + lid * 4]) = c1;
    *reinterpret_cast<float4*>(&s_colw[wid][256 + lid * 4]) = c2;
    *reinterpret_cast<float4*>(&s_colw[wid][384 + lid * 4]) = c3;

    float sq0 = a0.x * a0.x + a0.y * a0.y + a0.z * a0.z + a0.w * a0.w
              + a1.x * a1.x + a1.y * a1.y + a1.z * a1.z + a1.w * a1.w
              + a2.x * a2.x + a2.y * a2.y + a2.z * a2.z + a2.w * a2.w
              + a3.x * a3.x + a3.y * a3.y + a3.z * a3.z + a3.w * a3.w;
    float sq1 = b0.x * b0.x + b0.y * b0.y + b0.z * b0.z + b0.w * b0.w
              + b1.x * b1.x + b1.y * b1.y + b1.z * b1.z + b1.w * b1.w
              + b2.x * b2.x + b2.y * b2.y + b2.z * b2.z + b2.w * b2.w
              + b3.x * b3.x + b3.y * b3.y + b3.z * b3.z + b3.w * b3.w;

    // warp-reduce both row norms
    #pragma unroll
    for (int off = 16; off > 0; off >>= 1) {
        sq0 += __shfl_xor_sync(0xffffffffu, sq0, off);
        sq1 += __shfl_xor_sync(0xffffffffu, sq1, off);
    }
    if (lid == 0) {
        s_S[wid] = sq0 + sq1;
        s_M[wid] = fmaxf(sq0, sq1);
    }
    __syncthreads();

    // ---- block epilogue: combine 8 warps, push int64 atomics (replicated) ----
    const int rep = blockIdx.x & (NREP - 1);
    #pragma unroll
    for (int k = 0; k < 2; ++k) {
        const int c = tid + k * THREADS_A;
        float v = 0.f;
        #pragma unroll
        for (int w = 0; w < WARPS_A; ++w) v += s_colw[w][c];
        const long long q = __double2ll_rn((double)v * SCALE_D);
        atomicAdd(&g_col_ll[rep][c], (unsigned long long)q);
    }
    if (tid == 0) {
        float Sp = 0.f, Mp = 0.f;
        #pragma unroll
        for (int w = 0; w < WARPS_A; ++w) {
            Sp += s_S[w];
            Mp = fmaxf(Mp, s_M[w]);
        }
        atomicAdd(&g_S_ll, (unsigned long long)__double2ll_rn((double)Sp * SCALE_D));
        atomicMax(&g_max_int, __float_as_int(Mp));
        __threadfence();
        const unsigned int prev = atomicAdd(&g_counter, 1u);
        s_last = (prev == (unsigned int)(GRID_A - 1)) ? 1u : 0u;
    }
    __syncthreads();
    if (s_last == 0u) return;

    // ---- finalize: last block; accumulators are tiny and L2-hot ----
    __threadfence();

    long long t0 = 0ll, t1 = 0ll;
    #pragma unroll
    for (int r = 0; r < NREP; ++r) {
        t0 += (long long)g_col_ll[r][tid];
        t1 += (long long)g_col_ll[r][tid + THREADS_A];
    }
    const double d0 = (double)t0 * INV_SCALE;
    const double d1 = (double)t1 * INV_SCALE;

    s_red[tid] = d0 * d0 + d1 * d1;
    __syncthreads();
    #pragma unroll
    for (int s = THREADS_A / 2; s > 0; s >>= 1) {
        if (tid < s) s_red[tid] += s_red[tid + s];
        __syncthreads();
    }
    // all reads of g_col_ll are done (barrier above) -> safe to reset
    #pragma unroll
    for (int r = 0; r < NREP; ++r) {
        g_col_ll[r][tid] = 0ull;
        g_col_ll[r][tid + THREADS_A] = 0ull;
    }

    if (tid == 0) {
        const double ssq_total = s_red[0];
        const double S_total = (double)(long long)g_S_ll * INV_SCALE;
        const double maxsq = (double)__int_as_float(g_max_int);
        const double numer = (double)N_ROWS * S_total - ssq_total;
        const double norm = sqrt(maxsq);
        const double count = (double)N_ROWS * (double)(N_ROWS - 1) * 0.5;
        out[0] = (float)(numer / (norm * count));
        // reset scalars for next graph replay
        g_S_ll = 0ull;
        g_max_int = 0;
        g_counter = 0u;
    }
}

extern "C" void kernel_launch(void* const* d_in, const int* in_sizes, int n_in,
                              void* d_out, int out_size) {
    (void)in_sizes; (void)n_in; (void)out_size;
    const float* x = (const float*)d_in[0];
    float* out = (float*)d_out;
    fused_loss_kernel<<<GRID_A, THREADS_A>>>(x, out);
}